// round 3
// baseline (speedup 1.0000x reference)
#include <cuda_runtime.h>

// Problem constants (fixed shapes)
#define Bsz   128
#define Nn    512
#define RU    64
#define INPN  2
#define INSZ  66              // IN_PER_NODE + RU
#define OUTSZ 256             // 4*RU
#define MEMD  16
#define BOTD  4
#define BM    32              // batch chunk rows
#define NTHREADS 256
#define XSS   68              // padded xs row stride

#define W_ELEMS (INSZ*OUTSZ)          // 16896
#define SMEM_FLOATS (W_ELEMS + BM*XSS + MEMD + BOTD + OUTSZ)

__device__ __forceinline__ float fsigmoid(float x) {
    return __fdividef(1.0f, 1.0f + __expf(-x));
}
__device__ __forceinline__ float ftanh(float x) {
    // tanh(x) = 2*sigmoid(2x) - 1
    return 2.0f * fsigmoid(2.0f * x) - 1.0f;
}

__global__ __launch_bounds__(NTHREADS, 2)
void dlstm_kernel(const float* __restrict__ inputs,
                  const float* __restrict__ hx,
                  const float* __restrict__ cx,
                  const float* __restrict__ memory,
                  const float* __restrict__ w1,
                  const float* __restrict__ b1,
                  const float* __restrict__ w2,
                  const float* __restrict__ b2,
                  const float* __restrict__ w3,
                  const float* __restrict__ b3,
                  const float* __restrict__ b_out,
                  float* __restrict__ out)
{
    extern __shared__ float sm[];
    float* Ws   = sm;                          // [66][256]
    float* xs   = Ws + W_ELEMS;                // [32][68]
    float* memv = xs + BM * XSS;               // [16]
    float* botv = memv + MEMD;                 // [4]
    float* bo   = botv + BOTD;                 // [256]

    const int n    = blockIdx.x;
    const int tid  = threadIdx.x;
    const int warp = tid >> 5;
    const int lane = tid & 31;
    const int rub  = lane * 2;                 // ru base for this thread

    // ---- hypernetwork stage 1: mem = tanh(memory[n] @ w1 + b1) ----
    if (tid < MEMD) {
        float a = b1[tid];
        #pragma unroll
        for (int i = 0; i < MEMD; i++)
            a += memory[n * MEMD + i] * w1[i * MEMD + tid];
        memv[tid] = tanhf(a);
    }
    bo[tid] = b_out[tid];                      // 256 threads, 256 elems
    __syncthreads();

    // ---- stage 2: bot = tanh(mem @ w2 + b2) ----
    if (tid < BOTD) {
        float a = b2[tid];
        #pragma unroll
        for (int i = 0; i < MEMD; i++)
            a += memv[i] * w2[i * BOTD + tid];
        botv[tid] = tanhf(a);
    }
    __syncthreads();
    const float bt0 = botv[0], bt1 = botv[1], bt2 = botv[2], bt3 = botv[3];

    // ---- build W[n] = bot @ w3 + b3 into smem: layout [k][o] = k*256 + o ----
    {
        const float4* w3v = (const float4*)w3;
        const float4* b3v = (const float4*)b3;
        float4* Wv = (float4*)Ws;
        const int nv = W_ELEMS / 4;            // 4224
        for (int i = tid; i < nv; i += NTHREADS) {
            float4 a  = b3v[i];
            float4 g0 = w3v[i];
            float4 g1 = w3v[i + 1 * (W_ELEMS / 4)];
            float4 g2 = w3v[i + 2 * (W_ELEMS / 4)];
            float4 g3 = w3v[i + 3 * (W_ELEMS / 4)];
            a.x += bt0 * g0.x + bt1 * g1.x + bt2 * g2.x + bt3 * g3.x;
            a.y += bt0 * g0.y + bt1 * g1.y + bt2 * g2.y + bt3 * g3.y;
            a.z += bt0 * g0.z + bt1 * g1.z + bt2 * g2.z + bt3 * g3.z;
            a.w += bt0 * g0.w + bt1 * g1.w + bt2 * g2.w + bt3 * g3.w;
            Wv[i] = a;
        }
    }
    __syncthreads();

    const size_t outHalf = (size_t)Bsz * Nn * RU;

    // ---- main loop: 4 chunks of 32 batch rows ----
    for (int chunk = 0; chunk < Bsz; chunk += BM) {
        // load xs chunk: concat(input[b, n*2:(n+1)*2], hx[b, n*64:(n+1)*64])
        for (int i = tid; i < BM * INSZ; i += NTHREADS) {
            int r = i / INSZ;
            int k = i - r * INSZ;
            int b = chunk + r;
            float v;
            if (k < INPN) v = inputs[(size_t)b * (Nn * INPN) + n * INPN + k];
            else          v = hx[(size_t)b * (Nn * RU) + n * RU + (k - INPN)];
            xs[r * XSS + k] = v;
        }
        __syncthreads();

        // accumulators: [4 batch rows][2 ru][4 gates]
        float acc[4][2][4];
        #pragma unroll
        for (int i = 0; i < 4; i++)
            #pragma unroll
            for (int j = 0; j < 2; j++)
                #pragma unroll
                for (int g = 0; g < 4; g++)
                    acc[i][j][g] = 0.0f;

        const int brow0 = warp * 4;            // this warp's 4 batch rows (in chunk)

        #pragma unroll 2
        for (int k = 0; k < INSZ; k++) {
            float xv[4];
            #pragma unroll
            for (int i = 0; i < 4; i++)
                xv[i] = xs[(brow0 + i) * XSS + k];   // warp-broadcast

            const float* wr = Ws + k * OUTSZ + rub;
            float2 wv[4];
            wv[0] = *(const float2*)(wr);
            wv[1] = *(const float2*)(wr + 64);
            wv[2] = *(const float2*)(wr + 128);
            wv[3] = *(const float2*)(wr + 192);

            #pragma unroll
            for (int i = 0; i < 4; i++) {
                #pragma unroll
                for (int g = 0; g < 4; g++) {
                    acc[i][0][g] = fmaf(xv[i], wv[g].x, acc[i][0][g]);
                    acc[i][1][g] = fmaf(xv[i], wv[g].y, acc[i][1][g]);
                }
            }
        }

        // ---- epilogue: gates + LSTM state update ----
        #pragma unroll
        for (int i = 0; i < 4; i++) {
            int b = chunk + brow0 + i;
            size_t base = (size_t)b * (Nn * RU) + (size_t)n * RU + rub;
            float2 cxv = *(const float2*)(cx + base);
            float hyv[2], cyv[2];
            #pragma unroll
            for (int j = 0; j < 2; j++) {
                int ru = rub + j;
                float vi = fsigmoid(acc[i][j][0]) + bo[ru];
                float vf = fsigmoid(acc[i][j][1]) + bo[64 + ru];
                float vg = fsigmoid(acc[i][j][2]) + bo[128 + ru];
                float vo = fsigmoid(acc[i][j][3]) + bo[192 + ru];
                float it = fsigmoid(vi);
                float ft = fsigmoid(vf);
                float gt = ftanh(vg);
                float ot = fsigmoid(vo);
                float cxs = (j == 0) ? cxv.x : cxv.y;
                float c = cxs * ft + it * gt;
                cyv[j] = c;
                hyv[j] = ot * ftanh(c);
            }
            *(float2*)(out + base)           = make_float2(hyv[0], hyv[1]);
            *(float2*)(out + outHalf + base) = make_float2(cyv[0], cyv[1]);
        }
        __syncthreads();   // protect xs before next chunk overwrites it
    }
}

extern "C" void kernel_launch(void* const* d_in, const int* in_sizes, int n_in,
                              void* d_out, int out_size)
{
    const float* inputs = (const float*)d_in[0];
    const float* hx     = (const float*)d_in[1];
    const float* cx     = (const float*)d_in[2];
    const float* memory = (const float*)d_in[3];
    const float* w1     = (const float*)d_in[4];
    const float* b1     = (const float*)d_in[5];
    const float* w2     = (const float*)d_in[6];
    const float* b2     = (const float*)d_in[7];
    const float* w3     = (const float*)d_in[8];
    const float* b3     = (const float*)d_in[9];
    const float* b_out  = (const float*)d_in[10];
    float* out = (float*)d_out;

    const int smemBytes = SMEM_FLOATS * (int)sizeof(float);   // ~77.4 KB
    cudaFuncSetAttribute(dlstm_kernel,
                         cudaFuncAttributeMaxDynamicSharedMemorySize, smemBytes);

    dlstm_kernel<<<Nn, NTHREADS, smemBytes>>>(
        inputs, hx, cx, memory, w1, b1, w2, b2, w3, b3, b_out, out);
}

// round 4
// speedup vs baseline: 1.1247x; 1.1247x over previous
#include <cuda_runtime.h>

// Problem constants (fixed shapes)
#define Bsz   128
#define Nn    512
#define RU    64
#define INPN  2
#define INSZ  66              // IN_PER_NODE + RU
#define OUTSZ 256             // 4*RU
#define MEMD  16
#define BOTD  4
#define BM    32              // batch chunk rows
#define NTHREADS 256
#define XSS   68              // padded xs row stride

#define W_ELEMS (INSZ*OUTSZ)          // 16896
#define SMEM_FLOATS (W_ELEMS + BM*XSS + MEMD + BOTD + OUTSZ)

typedef unsigned long long ull;

__device__ __forceinline__ float fsigmoid(float x) {
    return __fdividef(1.0f, 1.0f + __expf(-x));
}
__device__ __forceinline__ float ftanh(float x) {
    // tanh(x) = 2*sigmoid(2x) - 1
    return 2.0f * fsigmoid(2.0f * x) - 1.0f;
}

// Packed 2xfp32 FMA (Blackwell f32x2 pipe, 2 FMAs per FMA-pipe issue)
__device__ __forceinline__ ull fma2(ull a, ull b, ull c) {
    ull d;
    asm("fma.rn.f32x2 %0, %1, %2, %3;" : "=l"(d) : "l"(a), "l"(b), "l"(c));
    return d;
}
__device__ __forceinline__ ull pack2(float lo, float hi) {
    ull d;
    asm("mov.b64 %0, {%1, %2};" : "=l"(d) : "f"(lo), "f"(hi));
    return d;
}
__device__ __forceinline__ void unpack2(ull v, float& lo, float& hi) {
    asm("mov.b64 {%0, %1}, %2;" : "=f"(lo), "=f"(hi) : "l"(v));
}

__global__ __launch_bounds__(NTHREADS, 2)
void dlstm_kernel(const float* __restrict__ inputs,
                  const float* __restrict__ hx,
                  const float* __restrict__ cx,
                  const float* __restrict__ memory,
                  const float* __restrict__ w1,
                  const float* __restrict__ b1,
                  const float* __restrict__ w2,
                  const float* __restrict__ b2,
                  const float* __restrict__ w3,
                  const float* __restrict__ b3,
                  const float* __restrict__ b_out,
                  float* __restrict__ out)
{
    extern __shared__ float sm[];
    float* Ws   = sm;                          // [66][256]
    float* xs   = Ws + W_ELEMS;                // [32][68]
    float* memv = xs + BM * XSS;               // [16]
    float* botv = memv + MEMD;                 // [4]
    float* bo   = botv + BOTD;                 // [256]

    const int n    = blockIdx.x;
    const int tid  = threadIdx.x;
    const int warp = tid >> 5;
    const int lane = tid & 31;
    const int rub  = lane * 2;                 // ru base for this thread

    // ---- hypernetwork stage 1: mem = tanh(memory[n] @ w1 + b1) ----
    if (tid < MEMD) {
        float a = b1[tid];
        #pragma unroll
        for (int i = 0; i < MEMD; i++)
            a += memory[n * MEMD + i] * w1[i * MEMD + tid];
        memv[tid] = tanhf(a);
    }
    bo[tid] = b_out[tid];                      // 256 threads, 256 elems
    __syncthreads();

    // ---- stage 2: bot = tanh(mem @ w2 + b2) ----
    if (tid < BOTD) {
        float a = b2[tid];
        #pragma unroll
        for (int i = 0; i < MEMD; i++)
            a += memv[i] * w2[i * BOTD + tid];
        botv[tid] = tanhf(a);
    }
    __syncthreads();
    const float bt0 = botv[0], bt1 = botv[1], bt2 = botv[2], bt3 = botv[3];

    // ---- build W[n] = bot @ w3 + b3 into smem: layout [k][o] = k*256 + o ----
    {
        const float4* w3v = (const float4*)w3;
        const float4* b3v = (const float4*)b3;
        float4* Wv = (float4*)Ws;
        const int nv = W_ELEMS / 4;            // 4224
        for (int i = tid; i < nv; i += NTHREADS) {
            float4 a  = b3v[i];
            float4 g0 = w3v[i];
            float4 g1 = w3v[i + 1 * (W_ELEMS / 4)];
            float4 g2 = w3v[i + 2 * (W_ELEMS / 4)];
            float4 g3 = w3v[i + 3 * (W_ELEMS / 4)];
            a.x += bt0 * g0.x + bt1 * g1.x + bt2 * g2.x + bt3 * g3.x;
            a.y += bt0 * g0.y + bt1 * g1.y + bt2 * g2.y + bt3 * g3.y;
            a.z += bt0 * g0.z + bt1 * g1.z + bt2 * g2.z + bt3 * g3.z;
            a.w += bt0 * g0.w + bt1 * g1.w + bt2 * g2.w + bt3 * g3.w;
            Wv[i] = a;
        }
    }
    __syncthreads();

    // hoist per-thread b_out values (constant across chunks)
    const float bo_i0 = bo[rub],       bo_i1 = bo[rub + 1];
    const float bo_f0 = bo[64 + rub],  bo_f1 = bo[64 + rub + 1];
    const float bo_g0 = bo[128 + rub], bo_g1 = bo[128 + rub + 1];
    const float bo_o0 = bo[192 + rub], bo_o1 = bo[192 + rub + 1];

    const size_t outHalf = (size_t)Bsz * Nn * RU;

    // ---- main loop: 4 chunks of 32 batch rows ----
    for (int chunk = 0; chunk < Bsz; chunk += BM) {
        // load xs chunk: concat(input[b, n*2:(n+1)*2], hx[b, n*64:(n+1)*64])
        for (int i = tid; i < BM * INSZ; i += NTHREADS) {
            int r = i / INSZ;
            int k = i - r * INSZ;
            int b = chunk + r;
            float v;
            if (k < INPN) v = inputs[(size_t)b * (Nn * INPN) + n * INPN + k];
            else          v = hx[(size_t)b * (Nn * RU) + n * RU + (k - INPN)];
            xs[r * XSS + k] = v;
        }
        __syncthreads();

        // packed accumulators: [4 batch rows][4 gates], each holds (ru, ru+1)
        ull acc[4][4];
        #pragma unroll
        for (int i = 0; i < 4; i++)
            #pragma unroll
            for (int g = 0; g < 4; g++)
                acc[i][g] = 0ull;

        const int brow0 = warp * 4;            // this warp's 4 batch rows (in chunk)
        const float* xrow = xs + brow0 * XSS;
        const float* wcol = Ws + rub;

        #pragma unroll 3
        for (int k = 0; k < INSZ; k++) {
            ull xp[4];
            #pragma unroll
            for (int i = 0; i < 4; i++) {
                float xv = xrow[i * XSS + k];          // warp-broadcast LDS
                xp[i] = pack2(xv, xv);
            }

            const float* wr = wcol + k * OUTSZ;
            ull wv[4];
            wv[0] = *(const ull*)(wr);
            wv[1] = *(const ull*)(wr + 64);
            wv[2] = *(const ull*)(wr + 128);
            wv[3] = *(const ull*)(wr + 192);

            #pragma unroll
            for (int i = 0; i < 4; i++) {
                #pragma unroll
                for (int g = 0; g < 4; g++)
                    acc[i][g] = fma2(xp[i], wv[g], acc[i][g]);
            }
        }

        // ---- epilogue: gates + LSTM state update ----
        #pragma unroll
        for (int i = 0; i < 4; i++) {
            int b = chunk + brow0 + i;
            size_t base = (size_t)b * (Nn * RU) + (size_t)n * RU + rub;
            float2 cxv = *(const float2*)(cx + base);

            float ai0, ai1, af0, af1, ag0, ag1, ao0, ao1;
            unpack2(acc[i][0], ai0, ai1);
            unpack2(acc[i][1], af0, af1);
            unpack2(acc[i][2], ag0, ag1);
            unpack2(acc[i][3], ao0, ao1);

            // lane j = 0
            float vi0 = fsigmoid(ai0) + bo_i0;
            float vf0 = fsigmoid(af0) + bo_f0;
            float vg0 = fsigmoid(ag0) + bo_g0;
            float vo0 = fsigmoid(ao0) + bo_o0;
            float c0  = cxv.x * fsigmoid(vf0) + fsigmoid(vi0) * ftanh(vg0);
            float h0  = fsigmoid(vo0) * ftanh(c0);
            // lane j = 1
            float vi1 = fsigmoid(ai1) + bo_i1;
            float vf1 = fsigmoid(af1) + bo_f1;
            float vg1 = fsigmoid(ag1) + bo_g1;
            float vo1 = fsigmoid(ao1) + bo_o1;
            float c1  = cxv.y * fsigmoid(vf1) + fsigmoid(vi1) * ftanh(vg1);
            float h1  = fsigmoid(vo1) * ftanh(c1);

            *(float2*)(out + base)           = make_float2(h0, h1);
            *(float2*)(out + outHalf + base) = make_float2(c0, c1);
        }
        __syncthreads();   // protect xs before next chunk overwrites it
    }
}

extern "C" void kernel_launch(void* const* d_in, const int* in_sizes, int n_in,
                              void* d_out, int out_size)
{
    const float* inputs = (const float*)d_in[0];
    const float* hx     = (const float*)d_in[1];
    const float* cx     = (const float*)d_in[2];
    const float* memory = (const float*)d_in[3];
    const float* w1     = (const float*)d_in[4];
    const float* b1     = (const float*)d_in[5];
    const float* w2     = (const float*)d_in[6];
    const float* b2     = (const float*)d_in[7];
    const float* w3     = (const float*)d_in[8];
    const float* b3     = (const float*)d_in[9];
    const float* b_out  = (const float*)d_in[10];
    float* out = (float*)d_out;

    const int smemBytes = SMEM_FLOATS * (int)sizeof(float);   // ~77.4 KB
    cudaFuncSetAttribute(dlstm_kernel,
                         cudaFuncAttributeMaxDynamicSharedMemorySize, smemBytes);

    dlstm_kernel<<<Nn, NTHREADS, smemBytes>>>(
        inputs, hx, cx, memory, w1, b1, w2, b2, w3, b3, b_out, out);
}

// round 6
// speedup vs baseline: 1.2376x; 1.1004x over previous
#include <cuda_runtime.h>

// Problem constants (fixed shapes)
#define Bsz   128
#define Nn    512
#define RU    64
#define INPN  2
#define INSZ  66              // IN_PER_NODE + RU
#define OUTSZ 256             // 4*RU
#define MEMD  16
#define BOTD  4
#define BM    64              // batch chunk rows (2 chunks of 64)
#define RPW   8               // rows per warp
#define NTHREADS 256
#define XSS   68              // padded xs row stride (even -> float2-aligned)

#define W_ELEMS (INSZ*OUTSZ)          // 16896
#define SMEM_FLOATS (W_ELEMS + BM*XSS + MEMD + BOTD + OUTSZ)

typedef unsigned long long ull;

__device__ __forceinline__ float fsigmoid(float x) {
    return __fdividef(1.0f, 1.0f + __expf(-x));
}
__device__ __forceinline__ float ftanh(float x) {
    return 2.0f * fsigmoid(2.0f * x) - 1.0f;
}

// Packed 2xfp32 FMA (Blackwell f32x2: 2 fp32 FMAs per FMA-pipe issue)
__device__ __forceinline__ ull fma2(ull a, ull b, ull c) {
    ull d;
    asm("fma.rn.f32x2 %0, %1, %2, %3;" : "=l"(d) : "l"(a), "l"(b), "l"(c));
    return d;
}
__device__ __forceinline__ ull pack2(float lo, float hi) {
    ull d;
    asm("mov.b64 %0, {%1, %2};" : "=l"(d) : "f"(lo), "f"(hi));
    return d;
}
__device__ __forceinline__ void unpack2(ull v, float& lo, float& hi) {
    asm("mov.b64 {%0, %1}, %2;" : "=f"(lo), "=f"(hi) : "l"(v));
}

__global__ __launch_bounds__(NTHREADS, 2)
void dlstm_kernel(const float* __restrict__ inputs,
                  const float* __restrict__ hx,
                  const float* __restrict__ cx,
                  const float* __restrict__ memory,
                  const float* __restrict__ w1,
                  const float* __restrict__ b1,
                  const float* __restrict__ w2,
                  const float* __restrict__ b2,
                  const float* __restrict__ w3,
                  const float* __restrict__ b3,
                  const float* __restrict__ b_out,
                  float* __restrict__ out)
{
    extern __shared__ float sm[];
    float* Ws   = sm;                          // [66][256]
    float* xs   = Ws + W_ELEMS;                // [64][68]
    float* memv = xs + BM * XSS;               // [16]
    float* botv = memv + MEMD;                 // [4]
    float* bo   = botv + BOTD;                 // [256]

    const int n    = blockIdx.x;
    const int tid  = threadIdx.x;
    const int warp = tid >> 5;
    const int lane = tid & 31;
    const int rub  = lane * 2;                 // ru base for this thread

    // ---- hypernetwork stage 1: mem = tanh(memory[n] @ w1 + b1) ----
    if (tid < MEMD) {
        float a = b1[tid];
        #pragma unroll
        for (int i = 0; i < MEMD; i++)
            a += memory[n * MEMD + i] * w1[i * MEMD + tid];
        memv[tid] = tanhf(a);
    }
    bo[tid] = b_out[tid];
    __syncthreads();

    // ---- stage 2: bot = tanh(mem @ w2 + b2) ----
    if (tid < BOTD) {
        float a = b2[tid];
        #pragma unroll
        for (int i = 0; i < MEMD; i++)
            a += memv[i] * w2[i * BOTD + tid];
        botv[tid] = tanhf(a);
    }
    __syncthreads();
    const float bt0 = botv[0], bt1 = botv[1], bt2 = botv[2], bt3 = botv[3];

    // ---- build W[n] = bot @ w3 + b3 into smem: layout [k][o] = k*256 + o ----
    {
        const float4* w3v = (const float4*)w3;
        const float4* b3v = (const float4*)b3;
        float4* Wv = (float4*)Ws;
        const int nv = W_ELEMS / 4;            // 4224
        for (int i = tid; i < nv; i += NTHREADS) {
            float4 a  = b3v[i];
            float4 g0 = w3v[i];
            float4 g1 = w3v[i + 1 * (W_ELEMS / 4)];
            float4 g2 = w3v[i + 2 * (W_ELEMS / 4)];
            float4 g3 = w3v[i + 3 * (W_ELEMS / 4)];
            a.x += bt0 * g0.x + bt1 * g1.x + bt2 * g2.x + bt3 * g3.x;
            a.y += bt0 * g0.y + bt1 * g1.y + bt2 * g2.y + bt3 * g3.y;
            a.z += bt0 * g0.z + bt1 * g1.z + bt2 * g2.z + bt3 * g3.z;
            a.w += bt0 * g0.w + bt1 * g1.w + bt2 * g2.w + bt3 * g3.w;
            Wv[i] = a;
        }
    }
    __syncthreads();

    // hoist per-thread b_out values
    const float bo_i0 = bo[rub],       bo_i1 = bo[rub + 1];
    const float bo_f0 = bo[64 + rub],  bo_f1 = bo[64 + rub + 1];
    const float bo_g0 = bo[128 + rub], bo_g1 = bo[128 + rub + 1];
    const float bo_o0 = bo[192 + rub], bo_o1 = bo[192 + rub + 1];

    const size_t outHalf = (size_t)Bsz * Nn * RU;

    // ---- main loop: 2 chunks of 64 batch rows, 8 rows per warp ----
    for (int chunk = 0; chunk < Bsz; chunk += BM) {
        // load xs chunk: concat(input[b, n*2:(n+1)*2], hx[b, n*64:(n+1)*64])
        for (int i = tid; i < BM * INSZ; i += NTHREADS) {
            int r = i / INSZ;
            int k = i - r * INSZ;
            int b = chunk + r;
            float v;
            if (k < INPN) v = inputs[(size_t)b * (Nn * INPN) + n * INPN + k];
            else          v = hx[(size_t)b * (Nn * RU) + n * RU + (k - INPN)];
            xs[r * XSS + k] = v;
        }
        __syncthreads();

        // packed accumulators: [8 batch rows][4 gates], each holds (ru, ru+1)
        ull acc[RPW][4];
        #pragma unroll
        for (int i = 0; i < RPW; i++)
            #pragma unroll
            for (int g = 0; g < 4; g++)
                acc[i][g] = 0ull;

        const int brow0 = warp * RPW;          // this warp's 8 batch rows (in chunk)
        const float* xrow = xs + brow0 * XSS;
        const float* wcol = Ws + rub;

        #pragma unroll 1
        for (int k2 = 0; k2 < INSZ; k2 += 2) {
            // two k values of x per row, via 64-bit broadcast LDS
            float2 xv[RPW];
            #pragma unroll
            for (int i = 0; i < RPW; i++)
                xv[i] = *(const float2*)(xrow + i * XSS + k2);

            // k = k2
            {
                const float* wr = wcol + k2 * OUTSZ;
                ull w0 = *(const ull*)(wr);
                ull w1v = *(const ull*)(wr + 64);
                ull w2v = *(const ull*)(wr + 128);
                ull w3v = *(const ull*)(wr + 192);
                #pragma unroll
                for (int i = 0; i < RPW; i++) {
                    ull xp = pack2(xv[i].x, xv[i].x);
                    acc[i][0] = fma2(xp, w0,  acc[i][0]);
                    acc[i][1] = fma2(xp, w1v, acc[i][1]);
                    acc[i][2] = fma2(xp, w2v, acc[i][2]);
                    acc[i][3] = fma2(xp, w3v, acc[i][3]);
                }
            }
            // k = k2 + 1
            {
                const float* wr = wcol + (k2 + 1) * OUTSZ;
                ull w0 = *(const ull*)(wr);
                ull w1v = *(const ull*)(wr + 64);
                ull w2v = *(const ull*)(wr + 128);
                ull w3v = *(const ull*)(wr + 192);
                #pragma unroll
                for (int i = 0; i < RPW; i++) {
                    ull xp = pack2(xv[i].y, xv[i].y);
                    acc[i][0] = fma2(xp, w0,  acc[i][0]);
                    acc[i][1] = fma2(xp, w1v, acc[i][1]);
                    acc[i][2] = fma2(xp, w2v, acc[i][2]);
                    acc[i][3] = fma2(xp, w3v, acc[i][3]);
                }
            }
        }

        // ---- epilogue: gates + LSTM state update ----
        #pragma unroll
        for (int i = 0; i < RPW; i++) {
            int b = chunk + brow0 + i;
            size_t base = (size_t)b * (Nn * RU) + (size_t)n * RU + rub;
            float2 cxv = *(const float2*)(cx + base);

            float ai0, ai1, af0, af1, ag0, ag1, ao0, ao1;
            unpack2(acc[i][0], ai0, ai1);
            unpack2(acc[i][1], af0, af1);
            unpack2(acc[i][2], ag0, ag1);
            unpack2(acc[i][3], ao0, ao1);

            float vi0 = fsigmoid(ai0) + bo_i0;
            float vf0 = fsigmoid(af0) + bo_f0;
            float vg0 = fsigmoid(ag0) + bo_g0;
            float vo0 = fsigmoid(ao0) + bo_o0;
            float c0  = cxv.x * fsigmoid(vf0) + fsigmoid(vi0) * ftanh(vg0);
            float h0  = fsigmoid(vo0) * ftanh(c0);

            float vi1 = fsigmoid(ai1) + bo_i1;
            float vf1 = fsigmoid(af1) + bo_f1;
            float vg1 = fsigmoid(ag1) + bo_g1;
            float vo1 = fsigmoid(ao1) + bo_o1;
            float c1  = cxv.y * fsigmoid(vf1) + fsigmoid(vi1) * ftanh(vg1);
            float h1  = fsigmoid(vo1) * ftanh(c1);

            *(float2*)(out + base)           = make_float2(h0, h1);
            *(float2*)(out + outHalf + base) = make_float2(c0, c1);
        }
        __syncthreads();   // protect xs before next chunk overwrites it
    }
}

extern "C" void kernel_launch(void* const* d_in, const int* in_sizes, int n_in,
                              void* d_out, int out_size)
{
    const float* inputs = (const float*)d_in[0];
    const float* hx     = (const float*)d_in[1];
    const float* cx     = (const float*)d_in[2];
    const float* memory = (const float*)d_in[3];
    const float* w1     = (const float*)d_in[4];
    const float* b1     = (const float*)d_in[5];
    const float* w2     = (const float*)d_in[6];
    const float* b2     = (const float*)d_in[7];
    const float* w3     = (const float*)d_in[8];
    const float* b3     = (const float*)d_in[9];
    const float* b_out  = (const float*)d_in[10];
    float* out = (float*)d_out;

    const int smemBytes = SMEM_FLOATS * (int)sizeof(float);   // ~86.1 KB
    cudaFuncSetAttribute(dlstm_kernel,
                         cudaFuncAttributeMaxDynamicSharedMemorySize, smemBytes);

    dlstm_kernel<<<Nn, NTHREADS, smemBytes>>>(
        inputs, hx, cx, memory, w1, b1, w2, b2, w3, b3, b_out, out);
}

// round 7
// speedup vs baseline: 1.7114x; 1.3829x over previous
#include <cuda_runtime.h>

// Problem constants (fixed shapes)
#define Bsz   128
#define Nn    512
#define RU    64
#define INPN  2
#define INSZ  66              // IN_PER_NODE + RU
#define OUTSZ 256             // 4*RU
#define MEMD  16
#define BOTD  4
#define BM    64              // batch chunk rows (2 chunks)
#define NTHREADS 256
#define KPAD  72              // INSZ padded to 9 k-steps of 8
#define NSTEP 9               // KPAD / 8
#define XSS   76              // xs row stride (76 mod 32 = 12 -> conflict-free A frags)
#define WS    264             // Ws row stride (264 mod 32 = 8 -> conflict-free B frags)

#define SMEM_FLOATS (KPAD*WS + BM*XSS + MEMD + BOTD + OUTSZ)

__device__ __forceinline__ float fsigmoid(float x) {
    return __fdividef(1.0f, 1.0f + __expf(-x));
}
__device__ __forceinline__ float ftanh(float x) {
    return 2.0f * fsigmoid(2.0f * x) - 1.0f;
}

// m16n8k8 tf32 MMA; fp32 operands passed as b32 (HW reads tf32 bit positions)
__device__ __forceinline__ void mma_tf32(float* c, const unsigned* a, const unsigned* b) {
    asm volatile(
        "mma.sync.aligned.m16n8k8.row.col.f32.tf32.tf32.f32 "
        "{%0,%1,%2,%3}, {%4,%5,%6,%7}, {%8,%9}, {%0,%1,%2,%3};"
        : "+f"(c[0]), "+f"(c[1]), "+f"(c[2]), "+f"(c[3])
        : "r"(a[0]), "r"(a[1]), "r"(a[2]), "r"(a[3]), "r"(b[0]), "r"(b[1]));
}

__global__ __launch_bounds__(NTHREADS, 2)
void dlstm_kernel(const float* __restrict__ inputs,
                  const float* __restrict__ hx,
                  const float* __restrict__ cx,
                  const float* __restrict__ memory,
                  const float* __restrict__ w1,
                  const float* __restrict__ b1,
                  const float* __restrict__ w2,
                  const float* __restrict__ b2,
                  const float* __restrict__ w3,
                  const float* __restrict__ b3,
                  const float* __restrict__ b_out,
                  float* __restrict__ out)
{
    extern __shared__ float sm[];
    float* Ws   = sm;                          // [KPAD][WS], rows 66..71 zero
    float* xs   = Ws + KPAD * WS;              // [BM][XSS], cols 66..71 zero
    float* memv = xs + BM * XSS;               // [16]
    float* botv = memv + MEMD;                 // [4]
    float* bo   = botv + BOTD;                 // [256]

    const int n    = blockIdx.x;
    const int tid  = threadIdx.x;
    const int wid  = tid >> 5;
    const int lane = tid & 31;
    const int gid  = lane >> 2;                // 0..7
    const int tig  = lane & 3;                 // 0..3
    const int warpM  = wid >> 2;               // 0..1  -> 32 m rows
    const int warpRu = wid & 3;                // 0..3  -> 16 ru columns

    // ---- hypernetwork stage 1 ----
    if (tid < MEMD) {
        float a = b1[tid];
        #pragma unroll
        for (int i = 0; i < MEMD; i++)
            a += memory[n * MEMD + i] * w1[i * MEMD + tid];
        memv[tid] = tanhf(a);
    }
    bo[tid] = b_out[tid];
    __syncthreads();

    // ---- stage 2 ----
    if (tid < BOTD) {
        float a = b2[tid];
        #pragma unroll
        for (int i = 0; i < MEMD; i++)
            a += memv[i] * w2[i * BOTD + tid];
        botv[tid] = tanhf(a);
    }
    __syncthreads();
    const float bt0 = botv[0], bt1 = botv[1], bt2 = botv[2], bt3 = botv[3];

    // ---- build W[n] = bot @ w3 + b3 into smem [k][o] with stride WS ----
    {
        const float4* w3v = (const float4*)w3;
        const float4* b3v = (const float4*)b3;
        const int nv = INSZ * OUTSZ / 4;       // 4224
        for (int i = tid; i < nv; i += NTHREADS) {
            int k  = i >> 6;                   // / (OUTSZ/4)
            int o4 = i & 63;
            float4 a  = b3v[i];
            float4 g0 = w3v[i];
            float4 g1 = w3v[i + 1 * nv];
            float4 g2 = w3v[i + 2 * nv];
            float4 g3 = w3v[i + 3 * nv];
            a.x += bt0 * g0.x + bt1 * g1.x + bt2 * g2.x + bt3 * g3.x;
            a.y += bt0 * g0.y + bt1 * g1.y + bt2 * g2.y + bt3 * g3.y;
            a.z += bt0 * g0.z + bt1 * g1.z + bt2 * g2.z + bt3 * g3.z;
            a.w += bt0 * g0.w + bt1 * g1.w + bt2 * g2.w + bt3 * g3.w;
            ((float4*)(Ws + k * WS))[o4] = a;
        }
        // zero pad rows 66..71 (cols 0..WS-1)
        for (int i = tid; i < (KPAD - INSZ) * WS; i += NTHREADS)
            Ws[INSZ * WS + i] = 0.0f;
    }
    __syncthreads();

    const size_t outHalf = (size_t)Bsz * Nn * RU;

    // ---- main loop: 2 chunks of 64 batch rows ----
    for (int chunk = 0; chunk < Bsz; chunk += BM) {
        // load xs chunk (KPAD cols: input | hx | zero-pad)
        for (int i = tid; i < BM * KPAD; i += NTHREADS) {
            int r = i / KPAD;
            int k = i - r * KPAD;
            int b = chunk + r;
            float v = 0.0f;
            if (k < INPN)      v = inputs[(size_t)b * (Nn * INPN) + n * INPN + k];
            else if (k < INSZ) v = hx[(size_t)b * (Nn * RU) + n * RU + (k - INPN)];
            xs[r * XSS + k] = v;
        }
        __syncthreads();

        // acc[mi][ni][c]: mi = m-frag (16 rows), ni = gate*2+h (8 n-frags of 8),
        // c-frag: rows {gid, gid+8}, cols {2tig, 2tig+1}
        float acc[2][8][4];
        #pragma unroll
        for (int mi = 0; mi < 2; mi++)
            #pragma unroll
            for (int ni = 0; ni < 8; ni++)
                #pragma unroll
                for (int c = 0; c < 4; c++)
                    acc[mi][ni][c] = 0.0f;

        const float* xbase = xs + (warpM * 32 + gid) * XSS + tig;
        const float* wbase = Ws + tig * WS + warpRu * 16 + gid;

        #pragma unroll 3
        for (int s = 0; s < NSTEP; s++) {
            const int k0 = s * 8;

            unsigned a[2][4];
            #pragma unroll
            for (int mi = 0; mi < 2; mi++) {
                const float* p = xbase + mi * (16 * XSS) + k0;
                a[mi][0] = __float_as_uint(p[0]);
                a[mi][1] = __float_as_uint(p[8 * XSS]);
                a[mi][2] = __float_as_uint(p[4]);
                a[mi][3] = __float_as_uint(p[8 * XSS + 4]);
            }

            unsigned b[8][4 / 2 * 1];  // [8][2]
            #pragma unroll
            for (int g = 0; g < 4; g++)
                #pragma unroll
                for (int h = 0; h < 2; h++) {
                    const float* p = wbase + (size_t)k0 * WS + g * 64 + h * 8;
                    b[g * 2 + h][0] = __float_as_uint(p[0]);
                    b[g * 2 + h][1] = __float_as_uint(p[4 * WS]);
                }

            #pragma unroll
            for (int mi = 0; mi < 2; mi++)
                #pragma unroll
                for (int ni = 0; ni < 8; ni++)
                    mma_tf32(acc[mi][ni], a[mi], b[ni]);
        }

        // ---- epilogue: gates + LSTM state update ----
        #pragma unroll
        for (int mi = 0; mi < 2; mi++) {
            #pragma unroll
            for (int rsel = 0; rsel < 2; rsel++) {
                int brow = chunk + warpM * 32 + mi * 16 + gid + rsel * 8;
                #pragma unroll
                for (int h = 0; h < 2; h++) {
                    int ru0 = warpRu * 16 + h * 8 + 2 * tig;
                    size_t base = (size_t)brow * (Nn * RU) + (size_t)n * RU + ru0;
                    float2 cxv = *(const float2*)(cx + base);
                    float hyv[2], cyv[2];
                    #pragma unroll
                    for (int c = 0; c < 2; c++) {
                        int ru = ru0 + c;
                        float ai = acc[mi][0 + h][rsel * 2 + c];
                        float af = acc[mi][2 + h][rsel * 2 + c];
                        float ag = acc[mi][4 + h][rsel * 2 + c];
                        float ao = acc[mi][6 + h][rsel * 2 + c];
                        float vi = fsigmoid(ai) + bo[ru];
                        float vf = fsigmoid(af) + bo[64 + ru];
                        float vg = fsigmoid(ag) + bo[128 + ru];
                        float vo = fsigmoid(ao) + bo[192 + ru];
                        float it = fsigmoid(vi);
                        float ft = fsigmoid(vf);
                        float gt = ftanh(vg);
                        float ot = fsigmoid(vo);
                        float cxs = (c == 0) ? cxv.x : cxv.y;
                        float cc = cxs * ft + it * gt;
                        cyv[c] = cc;
                        hyv[c] = ot * ftanh(cc);
                    }
                    *(float2*)(out + base)           = make_float2(hyv[0], hyv[1]);
                    *(float2*)(out + outHalf + base) = make_float2(cyv[0], cyv[1]);
                }
            }
        }
        __syncthreads();   // protect xs before next chunk overwrites it
    }
}

extern "C" void kernel_launch(void* const* d_in, const int* in_sizes, int n_in,
                              void* d_out, int out_size)
{
    const float* inputs = (const float*)d_in[0];
    const float* hx     = (const float*)d_in[1];
    const float* cx     = (const float*)d_in[2];
    const float* memory = (const float*)d_in[3];
    const float* w1     = (const float*)d_in[4];
    const float* b1     = (const float*)d_in[5];
    const float* w2     = (const float*)d_in[6];
    const float* b2     = (const float*)d_in[7];
    const float* w3     = (const float*)d_in[8];
    const float* b3     = (const float*)d_in[9];
    const float* b_out  = (const float*)d_in[10];
    float* out = (float*)d_out;

    const int smemBytes = SMEM_FLOATS * (int)sizeof(float);   // ~96.7 KB
    cudaFuncSetAttribute(dlstm_kernel,
                         cudaFuncAttributeMaxDynamicSharedMemorySize, smemBytes);

    dlstm_kernel<<<Nn, NTHREADS, smemBytes>>>(
        inputs, hx, cx, memory, w1, b1, w2, b2, w3, b3, b_out, out);
}

// round 8
// speedup vs baseline: 1.7603x; 1.0286x over previous
#include <cuda_runtime.h>

// Problem constants (fixed shapes)
#define Bsz   128
#define Nn    512
#define RU    64
#define INPN  2
#define INSZ  66              // IN_PER_NODE + RU
#define OUTSZ 256             // 4*RU
#define MEMD  16
#define BOTD  4
#define BM    64              // batch chunk rows (2 chunks)
#define NTHREADS 256
#define KPAD  72              // INSZ padded to 9 k-steps of 8
#define NSTEP 9               // KPAD / 8
#define XSS   76              // xs row stride (76 mod 32 = 12 -> conflict-free A frags)
#define WS    264             // Ws row stride (264 mod 32 = 8 -> conflict-free B frags)

#define SMEM_FLOATS (KPAD*WS + BM*XSS + MEMD + BOTD + OUTSZ)

__device__ __forceinline__ float fsigmoid(float x) {
    return __fdividef(1.0f, 1.0f + __expf(-x));
}
__device__ __forceinline__ float ftanh(float x) {
    return 2.0f * fsigmoid(2.0f * x) - 1.0f;
}

// m16n8k8 tf32 MMA; fp32 operands passed as b32 (HW reads tf32 bit positions)
__device__ __forceinline__ void mma_tf32(float* c, const unsigned* a, const unsigned* b) {
    asm volatile(
        "mma.sync.aligned.m16n8k8.row.col.f32.tf32.tf32.f32 "
        "{%0,%1,%2,%3}, {%4,%5,%6,%7}, {%8,%9}, {%0,%1,%2,%3};"
        : "+f"(c[0]), "+f"(c[1]), "+f"(c[2]), "+f"(c[3])
        : "r"(a[0]), "r"(a[1]), "r"(a[2]), "r"(a[3]), "r"(b[0]), "r"(b[1]));
}

__global__ __launch_bounds__(NTHREADS, 2)
void dlstm_kernel(const float* __restrict__ inputs,
                  const float* __restrict__ hx,
                  const float* __restrict__ cx,
                  const float* __restrict__ memory,
                  const float* __restrict__ w1,
                  const float* __restrict__ b1,
                  const float* __restrict__ w2,
                  const float* __restrict__ b2,
                  const float* __restrict__ w3,
                  const float* __restrict__ b3,
                  const float* __restrict__ b_out,
                  float* __restrict__ out)
{
    extern __shared__ float sm[];
    float* Ws   = sm;                          // [KPAD][WS], rows 66..71 zero
    float* xs   = Ws + KPAD * WS;              // [BM][XSS], cols 66..71 zero
    float* memv = xs + BM * XSS;               // [16]
    float* botv = memv + MEMD;                 // [4]
    float* bo   = botv + BOTD;                 // [256]

    const int n    = blockIdx.x;
    const int tid  = threadIdx.x;
    const int wid  = tid >> 5;
    const int lane = tid & 31;
    const int gid  = lane >> 2;                // 0..7
    const int tig  = lane & 3;                 // 0..3
    const int warpM  = wid >> 2;               // 0..1  -> 32 m rows
    const int warpRu = wid & 3;                // 0..3  -> 16 ru columns

    // ---- hypernetwork stage 1 ----
    if (tid < MEMD) {
        float a = b1[tid];
        #pragma unroll
        for (int i = 0; i < MEMD; i++)
            a += memory[n * MEMD + i] * w1[i * MEMD + tid];
        memv[tid] = tanhf(a);
    }
    bo[tid] = b_out[tid];
    __syncthreads();

    // ---- stage 2 ----
    if (tid < BOTD) {
        float a = b2[tid];
        #pragma unroll
        for (int i = 0; i < MEMD; i++)
            a += memv[i] * w2[i * BOTD + tid];
        botv[tid] = tanhf(a);
    }
    __syncthreads();
    const float bt0 = botv[0], bt1 = botv[1], bt2 = botv[2], bt3 = botv[3];

    // ---- build W[n] = bot @ w3 + b3 into smem [k][o] with stride WS ----
    {
        const float4* w3v = (const float4*)w3;
        const float4* b3v = (const float4*)b3;
        const int nv = INSZ * OUTSZ / 4;       // 4224
        for (int i = tid; i < nv; i += NTHREADS) {
            int k  = i >> 6;                   // / (OUTSZ/4)
            int o4 = i & 63;
            float4 a  = b3v[i];
            float4 g0 = w3v[i];
            float4 g1 = w3v[i + 1 * nv];
            float4 g2 = w3v[i + 2 * nv];
            float4 g3 = w3v[i + 3 * nv];
            a.x += bt0 * g0.x + bt1 * g1.x + bt2 * g2.x + bt3 * g3.x;
            a.y += bt0 * g0.y + bt1 * g1.y + bt2 * g2.y + bt3 * g3.y;
            a.z += bt0 * g0.z + bt1 * g1.z + bt2 * g2.z + bt3 * g3.z;
            a.w += bt0 * g0.w + bt1 * g1.w + bt2 * g2.w + bt3 * g3.w;
            ((float4*)(Ws + k * WS))[o4] = a;
        }
        // zero pad rows 66..71 (cols 0..WS-1)
        for (int i = tid; i < (KPAD - INSZ) * WS; i += NTHREADS)
            Ws[INSZ * WS + i] = 0.0f;
    }
    __syncthreads();

    const size_t outHalf = (size_t)Bsz * Nn * RU;

    // ---- main loop: 2 chunks of 64 batch rows ----
    for (int chunk = 0; chunk < Bsz; chunk += BM) {
        // load xs chunk (KPAD cols: input | hx | zero-pad)
        for (int i = tid; i < BM * KPAD; i += NTHREADS) {
            int r = i / KPAD;
            int k = i - r * KPAD;
            int b = chunk + r;
            float v = 0.0f;
            if (k < INPN)      v = inputs[(size_t)b * (Nn * INPN) + n * INPN + k];
            else if (k < INSZ) v = hx[(size_t)b * (Nn * RU) + n * RU + (k - INPN)];
            xs[r * XSS + k] = v;
        }
        __syncthreads();

        // acc[mi][ni][c]: mi = m-frag (16 rows), ni = gate*2+h (8 n-frags of 8),
        // c-frag: rows {gid, gid+8}, cols {2tig, 2tig+1}
        float acc[2][8][4];
        #pragma unroll
        for (int mi = 0; mi < 2; mi++)
            #pragma unroll
            for (int ni = 0; ni < 8; ni++)
                #pragma unroll
                for (int c = 0; c < 4; c++)
                    acc[mi][ni][c] = 0.0f;

        const float* xbase = xs + (warpM * 32 + gid) * XSS + tig;
        const float* wbase = Ws + tig * WS + warpRu * 16 + gid;

        #pragma unroll 3
        for (int s = 0; s < NSTEP; s++) {
            const int k0 = s * 8;

            unsigned a[2][4];
            #pragma unroll
            for (int mi = 0; mi < 2; mi++) {
                const float* p = xbase + mi * (16 * XSS) + k0;
                a[mi][0] = __float_as_uint(p[0]);
                a[mi][1] = __float_as_uint(p[8 * XSS]);
                a[mi][2] = __float_as_uint(p[4]);
                a[mi][3] = __float_as_uint(p[8 * XSS + 4]);
            }

            unsigned b[8][4 / 2 * 1];  // [8][2]
            #pragma unroll
            for (int g = 0; g < 4; g++)
                #pragma unroll
                for (int h = 0; h < 2; h++) {
                    const float* p = wbase + (size_t)k0 * WS + g * 64 + h * 8;
                    b[g * 2 + h][0] = __float_as_uint(p[0]);
                    b[g * 2 + h][1] = __float_as_uint(p[4 * WS]);
                }

            #pragma unroll
            for (int mi = 0; mi < 2; mi++)
                #pragma unroll
                for (int ni = 0; ni < 8; ni++)
                    mma_tf32(acc[mi][ni], a[mi], b[ni]);
        }

        // ---- epilogue: gates + LSTM state update ----
        #pragma unroll
        for (int mi = 0; mi < 2; mi++) {
            #pragma unroll
            for (int rsel = 0; rsel < 2; rsel++) {
                int brow = chunk + warpM * 32 + mi * 16 + gid + rsel * 8;
                #pragma unroll
                for (int h = 0; h < 2; h++) {
                    int ru0 = warpRu * 16 + h * 8 + 2 * tig;
                    size_t base = (size_t)brow * (Nn * RU) + (size_t)n * RU + ru0;
                    float2 cxv = *(const float2*)(cx + base);
                    float hyv[2], cyv[2];
                    #pragma unroll
                    for (int c = 0; c < 2; c++) {
                        int ru = ru0 + c;
                        float ai = acc[mi][0 + h][rsel * 2 + c];
                        float af = acc[mi][2 + h][rsel * 2 + c];
                        float ag = acc[mi][4 + h][rsel * 2 + c];
                        float ao = acc[mi][6 + h][rsel * 2 + c];
                        float vi = fsigmoid(ai) + bo[ru];
                        float vf = fsigmoid(af) + bo[64 + ru];
                        float vg = fsigmoid(ag) + bo[128 + ru];
                        float vo = fsigmoid(ao) + bo[192 + ru];
                        float it = fsigmoid(vi);
                        float ft = fsigmoid(vf);
                        float gt = ftanh(vg);
                        float ot = fsigmoid(vo);
                        float cxs = (c == 0) ? cxv.x : cxv.y;
                        float cc = cxs * ft + it * gt;
                        cyv[c] = cc;
                        hyv[c] = ot * ftanh(cc);
                    }
                    *(float2*)(out + base)           = make_float2(hyv[0], hyv[1]);
                    *(float2*)(out + outHalf + base) = make_float2(cyv[0], cyv[1]);
                }
            }
        }
        __syncthreads();   // protect xs before next chunk overwrites it
    }
}

extern "C" void kernel_launch(void* const* d_in, const int* in_sizes, int n_in,
                              void* d_out, int out_size)
{
    const float* inputs = (const float*)d_in[0];
    const float* hx     = (const float*)d_in[1];
    const float* cx     = (const float*)d_in[2];
    const float* memory = (const float*)d_in[3];
    const float* w1     = (const float*)d_in[4];
    const float* b1     = (const float*)d_in[5];
    const float* w2     = (const float*)d_in[6];
    const float* b2     = (const float*)d_in[7];
    const float* w3     = (const float*)d_in[8];
    const float* b3     = (const float*)d_in[9];
    const float* b_out  = (const float*)d_in[10];
    float* out = (float*)d_out;

    const int smemBytes = SMEM_FLOATS * (int)sizeof(float);   // ~96.7 KB
    cudaFuncSetAttribute(dlstm_kernel,
                         cudaFuncAttributeMaxDynamicSharedMemorySize, smemBytes);

    dlstm_kernel<<<Nn, NTHREADS, smemBytes>>>(
        inputs, hx, cx, memory, w1, b1, w2, b2, w3, b3, b_out, out);
}

// round 10
// speedup vs baseline: 1.7613x; 1.0006x over previous
#include <cuda_runtime.h>

// Problem constants (fixed shapes)
#define Bsz   128
#define Nn    512
#define RU    64
#define INPN  2
#define INSZ  66              // IN_PER_NODE + RU
#define OUTSZ 256             // 4*RU
#define MEMD  16
#define BOTD  4
#define BM    64              // batch chunk rows (2 chunks)
#define NTHREADS 256
#define KPAD  72              // INSZ padded to 9 k-steps of 8
#define NSTEP 9               // KPAD / 8
#define XSS   76              // xs row stride (76 mod 32 = 12 -> conflict-free A frags)
#define WS    264             // Ws row stride (264 mod 32 = 8 -> conflict-free B frags)

#define SMEM_FLOATS (KPAD*WS + BM*XSS + MEMD + BOTD + OUTSZ)

__device__ __forceinline__ float fsigmoid(float x) {
    return __fdividef(1.0f, 1.0f + __expf(-x));
}
__device__ __forceinline__ float ftanh(float x) {
    return 2.0f * fsigmoid(2.0f * x) - 1.0f;
}

// m16n8k8 tf32 MMA; fp32 operands passed as b32 (HW reads tf32 bit positions)
__device__ __forceinline__ void mma_tf32(float* c, const unsigned* a, const unsigned* b) {
    asm volatile(
        "mma.sync.aligned.m16n8k8.row.col.f32.tf32.tf32.f32 "
        "{%0,%1,%2,%3}, {%4,%5,%6,%7}, {%8,%9}, {%0,%1,%2,%3};"
        : "+f"(c[0]), "+f"(c[1]), "+f"(c[2]), "+f"(c[3])
        : "r"(a[0]), "r"(a[1]), "r"(a[2]), "r"(a[3]), "r"(b[0]), "r"(b[1]));
}

__global__ __launch_bounds__(NTHREADS, 2)
void dlstm_kernel(const float* __restrict__ inputs,
                  const float* __restrict__ hx,
                  const float* __restrict__ cx,
                  const float* __restrict__ memory,
                  const float* __restrict__ w1,
                  const float* __restrict__ b1,
                  const float* __restrict__ w2,
                  const float* __restrict__ b2,
                  const float* __restrict__ w3,
                  const float* __restrict__ b3,
                  const float* __restrict__ b_out,
                  float* __restrict__ out)
{
    extern __shared__ float sm[];
    float* Ws   = sm;                          // [KPAD][WS], rows 66..71 zero
    float* xs   = Ws + KPAD * WS;              // [BM][XSS], cols 66..71 zero
    float* memv = xs + BM * XSS;               // [16]
    float* botv = memv + MEMD;                 // [4]
    float* bo   = botv + BOTD;                 // [256]

    const int n    = blockIdx.x;
    const int tid  = threadIdx.x;
    const int wid  = tid >> 5;
    const int lane = tid & 31;
    const int gid  = lane >> 2;                // 0..7
    const int tig  = lane & 3;                 // 0..3
    const int warpM  = wid >> 2;               // 0..1  -> 32 m rows
    const int warpRu = wid & 3;                // 0..3  -> 16 ru columns

    // ---- hypernetwork stage 1 ----
    if (tid < MEMD) {
        float a = b1[tid];
        #pragma unroll
        for (int i = 0; i < MEMD; i++)
            a += memory[n * MEMD + i] * w1[i * MEMD + tid];
        memv[tid] = tanhf(a);
    }
    bo[tid] = b_out[tid];
    __syncthreads();

    // ---- stage 2 ----
    if (tid < BOTD) {
        float a = b2[tid];
        #pragma unroll
        for (int i = 0; i < MEMD; i++)
            a += memv[i] * w2[i * BOTD + tid];
        botv[tid] = tanhf(a);
    }
    __syncthreads();
    const float bt0 = botv[0], bt1 = botv[1], bt2 = botv[2], bt3 = botv[3];

    // ---- build W[n] = bot @ w3 + b3 into smem [k][o] with stride WS ----
    {
        const float4* w3v = (const float4*)w3;
        const float4* b3v = (const float4*)b3;
        const int nv = INSZ * OUTSZ / 4;       // 4224
        for (int i = tid; i < nv; i += NTHREADS) {
            int k  = i >> 6;                   // / (OUTSZ/4)
            int o4 = i & 63;
            float4 a  = b3v[i];
            float4 g0 = w3v[i];
            float4 g1 = w3v[i + 1 * nv];
            float4 g2 = w3v[i + 2 * nv];
            float4 g3 = w3v[i + 3 * nv];
            a.x += bt0 * g0.x + bt1 * g1.x + bt2 * g2.x + bt3 * g3.x;
            a.y += bt0 * g0.y + bt1 * g1.y + bt2 * g2.y + bt3 * g3.y;
            a.z += bt0 * g0.z + bt1 * g1.z + bt2 * g2.z + bt3 * g3.z;
            a.w += bt0 * g0.w + bt1 * g1.w + bt2 * g2.w + bt3 * g3.w;
            ((float4*)(Ws + k * WS))[o4] = a;
        }
        // zero pad rows 66..71 (cols 0..WS-1)
        for (int i = tid; i < (KPAD - INSZ) * WS; i += NTHREADS)
            Ws[INSZ * WS + i] = 0.0f;
    }
    __syncthreads();

    const size_t outHalf = (size_t)Bsz * Nn * RU;

    // ---- main loop: 2 chunks of 64 batch rows ----
    for (int chunk = 0; chunk < Bsz; chunk += BM) {
        // load xs chunk (KPAD cols: input | hx | zero-pad)
        for (int i = tid; i < BM * KPAD; i += NTHREADS) {
            int r = i / KPAD;
            int k = i - r * KPAD;
            int b = chunk + r;
            float v = 0.0f;
            if (k < INPN)      v = inputs[(size_t)b * (Nn * INPN) + n * INPN + k];
            else if (k < INSZ) v = hx[(size_t)b * (Nn * RU) + n * RU + (k - INPN)];
            xs[r * XSS + k] = v;
        }
        __syncthreads();

        // acc[mi][ni][c]: mi = m-frag (16 rows), ni = gate*2+h (8 n-frags of 8),
        // c-frag: rows {gid, gid+8}, cols {2tig, 2tig+1}
        float acc[2][8][4];
        #pragma unroll
        for (int mi = 0; mi < 2; mi++)
            #pragma unroll
            for (int ni = 0; ni < 8; ni++)
                #pragma unroll
                for (int c = 0; c < 4; c++)
                    acc[mi][ni][c] = 0.0f;

        const float* xbase = xs + (warpM * 32 + gid) * XSS + tig;
        const float* wbase = Ws + tig * WS + warpRu * 16 + gid;

        #pragma unroll 3
        for (int s = 0; s < NSTEP; s++) {
            const int k0 = s * 8;

            unsigned a[2][4];
            #pragma unroll
            for (int mi = 0; mi < 2; mi++) {
                const float* p = xbase + mi * (16 * XSS) + k0;
                a[mi][0] = __float_as_uint(p[0]);
                a[mi][1] = __float_as_uint(p[8 * XSS]);
                a[mi][2] = __float_as_uint(p[4]);
                a[mi][3] = __float_as_uint(p[8 * XSS + 4]);
            }

            unsigned b[8][4 / 2 * 1];  // [8][2]
            #pragma unroll
            for (int g = 0; g < 4; g++)
                #pragma unroll
                for (int h = 0; h < 2; h++) {
                    const float* p = wbase + (size_t)k0 * WS + g * 64 + h * 8;
                    b[g * 2 + h][0] = __float_as_uint(p[0]);
                    b[g * 2 + h][1] = __float_as_uint(p[4 * WS]);
                }

            #pragma unroll
            for (int mi = 0; mi < 2; mi++)
                #pragma unroll
                for (int ni = 0; ni < 8; ni++)
                    mma_tf32(acc[mi][ni], a[mi], b[ni]);
        }

        // ---- epilogue: gates + LSTM state update ----
        #pragma unroll
        for (int mi = 0; mi < 2; mi++) {
            #pragma unroll
            for (int rsel = 0; rsel < 2; rsel++) {
                int brow = chunk + warpM * 32 + mi * 16 + gid + rsel * 8;
                #pragma unroll
                for (int h = 0; h < 2; h++) {
                    int ru0 = warpRu * 16 + h * 8 + 2 * tig;
                    size_t base = (size_t)brow * (Nn * RU) + (size_t)n * RU + ru0;
                    float2 cxv = *(const float2*)(cx + base);
                    float hyv[2], cyv[2];
                    #pragma unroll
                    for (int c = 0; c < 2; c++) {
                        int ru = ru0 + c;
                        float ai = acc[mi][0 + h][rsel * 2 + c];
                        float af = acc[mi][2 + h][rsel * 2 + c];
                        float ag = acc[mi][4 + h][rsel * 2 + c];
                        float ao = acc[mi][6 + h][rsel * 2 + c];
                        float vi = fsigmoid(ai) + bo[ru];
                        float vf = fsigmoid(af) + bo[64 + ru];
                        float vg = fsigmoid(ag) + bo[128 + ru];
                        float vo = fsigmoid(ao) + bo[192 + ru];
                        float it = fsigmoid(vi);
                        float ft = fsigmoid(vf);
                        float gt = ftanh(vg);
                        float ot = fsigmoid(vo);
                        float cxs = (c == 0) ? cxv.x : cxv.y;
                        float cc = cxs * ft + it * gt;
                        cyv[c] = cc;
                        hyv[c] = ot * ftanh(cc);
                    }
                    *(float2*)(out + base)           = make_float2(hyv[0], hyv[1]);
                    *(float2*)(out + outHalf + base) = make_float2(cyv[0], cyv[1]);
                }
            }
        }
        __syncthreads();   // protect xs before next chunk overwrites it
    }
}

extern "C" void kernel_launch(void* const* d_in, const int* in_sizes, int n_in,
                              void* d_out, int out_size)
{
    const float* inputs = (const float*)d_in[0];
    const float* hx     = (const float*)d_in[1];
    const float* cx     = (const float*)d_in[2];
    const float* memory = (const float*)d_in[3];
    const float* w1     = (const float*)d_in[4];
    const float* b1     = (const float*)d_in[5];
    const float* w2     = (const float*)d_in[6];
    const float* b2     = (const float*)d_in[7];
    const float* w3     = (const float*)d_in[8];
    const float* b3     = (const float*)d_in[9];
    const float* b_out  = (const float*)d_in[10];
    float* out = (float*)d_out;

    const int smemBytes = SMEM_FLOATS * (int)sizeof(float);   // ~96.7 KB
    cudaFuncSetAttribute(dlstm_kernel,
                         cudaFuncAttributeMaxDynamicSharedMemorySize, smemBytes);

    dlstm_kernel<<<Nn, NTHREADS, smemBytes>>>(
        inputs, hx, cx, memory, w1, b1, w2, b2, w3, b3, b_out, out);
}